// round 1
// baseline (speedup 1.0000x reference)
#include <cuda_runtime.h>
#include <math.h>

// Problem shape (fixed by setup_inputs)
#define N_FEAT  32768
#define M_PROTO 2048
#define K_DIM   512

// GEMM tiling
#define BM 128
#define BN 128
#define BK 16
#define TM 8
#define TN 8

// Scratch for prototype squared norms (no cudaMalloc allowed)
__device__ float g_psq[M_PROTO];

// ---------------------------------------------------------------------------
// ||p_m||^2 for each prototype row
// ---------------------------------------------------------------------------
__global__ void psq_kernel(const float* __restrict__ B) {
    int m = blockIdx.x * blockDim.x + threadIdx.x;
    if (m >= M_PROTO) return;
    const float4* row = (const float4*)(B + (size_t)m * K_DIM);
    float s = 0.f;
#pragma unroll 8
    for (int i = 0; i < K_DIM / 4; i++) {
        float4 v = row[i];
        s += v.x * v.x + v.y * v.y + v.z * v.z + v.w * v.w;
    }
    g_psq[m] = s;
}

// ---------------------------------------------------------------------------
// S[n,m] = 20 * dot(feat[n], proto[m]) - 10 * ||p_m||^2
// (softmax logits; the per-row -10*||f_n||^2 constant is shift-invariant
//  under softmax and is dropped)
// A: [N_FEAT, K_DIM] row-major, B: [M_PROTO, K_DIM] row-major,
// S: [N_FEAT, M_PROTO]
// ---------------------------------------------------------------------------
__global__ __launch_bounds__(256, 2)
void gemm_logits_kernel(const float* __restrict__ A,
                        const float* __restrict__ B,
                        float* __restrict__ S) {
    __shared__ float As[BK][BM];
    __shared__ float Bs[BK][BN];

    const int tid = threadIdx.x;             // 0..255
    const int m0  = blockIdx.x * BN;         // prototype tile offset
    const int n0  = blockIdx.y * BM;         // feature tile offset

    const int tx = tid & 15;                 // proto sub-tile (0..15)
    const int ty = tid >> 4;                 // feat  sub-tile (0..15)

    float acc[TM][TN];
#pragma unroll
    for (int i = 0; i < TM; i++)
#pragma unroll
        for (int j = 0; j < TN; j++) acc[i][j] = 0.f;

    float4 pa[2], pb[2];

    // prefetch k-tile 0 into registers
#pragma unroll
    for (int i = 0; i < 2; i++) {
        int v  = tid * 2 + i;                // 0..511
        int r  = v >> 2;                     // row within tile (0..127)
        int c4 = v & 3;                      // which float4 in the 16-wide k slab
        pa[i] = *(const float4*)(A + (size_t)(n0 + r) * K_DIM + c4 * 4);
        pb[i] = *(const float4*)(B + (size_t)(m0 + r) * K_DIM + c4 * 4);
    }

    const int KT = K_DIM / BK;               // 32
    for (int kt = 0; kt < KT; kt++) {
        // registers -> smem (transposed: As[k][row])
#pragma unroll
        for (int i = 0; i < 2; i++) {
            int v  = tid * 2 + i;
            int r  = v >> 2;
            int c4 = v & 3;
            As[c4 * 4 + 0][r] = pa[i].x;
            As[c4 * 4 + 1][r] = pa[i].y;
            As[c4 * 4 + 2][r] = pa[i].z;
            As[c4 * 4 + 3][r] = pa[i].w;
            Bs[c4 * 4 + 0][r] = pb[i].x;
            Bs[c4 * 4 + 1][r] = pb[i].y;
            Bs[c4 * 4 + 2][r] = pb[i].z;
            Bs[c4 * 4 + 3][r] = pb[i].w;
        }
        __syncthreads();

        // prefetch next k-tile while computing on the current one
        if (kt + 1 < KT) {
            int k0 = (kt + 1) * BK;
#pragma unroll
            for (int i = 0; i < 2; i++) {
                int v  = tid * 2 + i;
                int r  = v >> 2;
                int c4 = v & 3;
                pa[i] = *(const float4*)(A + (size_t)(n0 + r) * K_DIM + k0 + c4 * 4);
                pb[i] = *(const float4*)(B + (size_t)(m0 + r) * K_DIM + k0 + c4 * 4);
            }
        }

#pragma unroll
        for (int k = 0; k < BK; k++) {
            float a[TM], b[TN];
            *(float4*)&a[0] = *(const float4*)&As[k][ty * TM + 0];
            *(float4*)&a[4] = *(const float4*)&As[k][ty * TM + 4];
            *(float4*)&b[0] = *(const float4*)&Bs[k][tx * TN + 0];
            *(float4*)&b[4] = *(const float4*)&Bs[k][tx * TN + 4];
#pragma unroll
            for (int i = 0; i < TM; i++)
#pragma unroll
                for (int j = 0; j < TN; j++)
                    acc[i][j] = fmaf(a[i], b[j], acc[i][j]);
        }
        __syncthreads();
    }

    // epilogue: logits = 20*cross - 10*psq
    float psq[TN];
#pragma unroll
    for (int j = 0; j < TN; j++) psq[j] = g_psq[m0 + tx * TN + j];

#pragma unroll
    for (int i = 0; i < TM; i++) {
        size_t row = (size_t)(n0 + ty * TM + i);
        float4 o0, o1;
        o0.x = 20.f * acc[i][0] - 10.f * psq[0];
        o0.y = 20.f * acc[i][1] - 10.f * psq[1];
        o0.z = 20.f * acc[i][2] - 10.f * psq[2];
        o0.w = 20.f * acc[i][3] - 10.f * psq[3];
        o1.x = 20.f * acc[i][4] - 10.f * psq[4];
        o1.y = 20.f * acc[i][5] - 10.f * psq[5];
        o1.z = 20.f * acc[i][6] - 10.f * psq[6];
        o1.w = 20.f * acc[i][7] - 10.f * psq[7];
        *(float4*)(S + row * M_PROTO + m0 + tx * TN + 0) = o0;
        *(float4*)(S + row * M_PROTO + m0 + tx * TN + 4) = o1;
    }
}

// ---------------------------------------------------------------------------
// Row softmax (in place on S), plus quality = max prob = 1/sum(exp),
// max_id = argmax (first occurrence, matching jnp.argmax).
// One block (256 threads) per row; 8 contiguous elements per thread.
// ---------------------------------------------------------------------------
__global__ void softmax_kernel(float* __restrict__ S,
                               float* __restrict__ quality,
                               float* __restrict__ maxid) {
    const int row = blockIdx.x;
    float* srow = S + (size_t)row * M_PROTO;
    const int t = threadIdx.x;

    float v[8];
    float4 v0 = *(const float4*)(srow + t * 8 + 0);
    float4 v1 = *(const float4*)(srow + t * 8 + 4);
    v[0] = v0.x; v[1] = v0.y; v[2] = v0.z; v[3] = v0.w;
    v[4] = v1.x; v[5] = v1.y; v[6] = v1.z; v[7] = v1.w;

    // per-thread max/argmax (strict >, ascending index => first occurrence)
    float lmax = v[0];
    int   limx = t * 8;
#pragma unroll
    for (int j = 1; j < 8; j++) {
        if (v[j] > lmax) { lmax = v[j]; limx = t * 8 + j; }
    }

    __shared__ float smax[256];
    __shared__ int   sidx[256];
    smax[t] = lmax;
    sidx[t] = limx;
    __syncthreads();
#pragma unroll
    for (int s = 128; s > 0; s >>= 1) {
        if (t < s) {
            float v2 = smax[t + s];
            int   i2 = sidx[t + s];
            if (v2 > smax[t] || (v2 == smax[t] && i2 < sidx[t])) {
                smax[t] = v2;
                sidx[t] = i2;
            }
        }
        __syncthreads();
    }
    const float rowmax = smax[0];
    const int   rowarg = sidx[0];
    __syncthreads();

    float e[8];
    float lsum = 0.f;
#pragma unroll
    for (int j = 0; j < 8; j++) {
        e[j] = expf(v[j] - rowmax);
        lsum += e[j];
    }
    smax[t] = lsum;
    __syncthreads();
#pragma unroll
    for (int s = 128; s > 0; s >>= 1) {
        if (t < s) smax[t] += smax[t + s];
        __syncthreads();
    }
    const float inv = 1.0f / smax[0];

    float4 o0, o1;
    o0.x = e[0] * inv; o0.y = e[1] * inv; o0.z = e[2] * inv; o0.w = e[3] * inv;
    o1.x = e[4] * inv; o1.y = e[5] * inv; o1.z = e[6] * inv; o1.w = e[7] * inv;
    *(float4*)(srow + t * 8 + 0) = o0;
    *(float4*)(srow + t * 8 + 4) = o1;

    if (t == 0) {
        quality[row] = inv;              // exp(max-max)=1 -> max prob = 1/sum
        maxid[row]   = (float)rowarg;
    }
}

// ---------------------------------------------------------------------------
extern "C" void kernel_launch(void* const* d_in, const int* in_sizes, int n_in,
                              void* d_out, int out_size) {
    const float* feat  = (const float*)d_in[0];   // [32768, 512]
    const float* proto = (const float*)d_in[1];   // [2048, 512]
    float* out = (float*)d_out;

    // output layout (reference return order, flattened):
    //   [0, N)        quality
    //   [N, 2N)       max_id (cast to float)
    //   [2N, 2N+N*M)  prediction
    float* quality = out;
    float* maxid   = out + N_FEAT;
    float* pred    = out + 2 * N_FEAT;

    psq_kernel<<<M_PROTO / 256, 256>>>(proto);

    dim3 grid(M_PROTO / BN, N_FEAT / BM);
    gemm_logits_kernel<<<grid, 256>>>(feat, proto, pred);

    softmax_kernel<<<N_FEAT, 256>>>(pred, quality, maxid);
}

// round 4
// speedup vs baseline: 1.3478x; 1.3478x over previous
#include <cuda_runtime.h>
#include <math.h>
#include <stdint.h>

// Problem shape (fixed by setup_inputs)
#define N_FEAT  32768
#define M_PROTO 2048
#define K_DIM   512

// ---------------------------------------------------------------------------
// Static device scratch (no cudaMalloc allowed)
// hi/lo tf32 splits, k-permuted within groups of 8 so that logical columns
// (c, c+4) sit at physical (2c, 2c+1)  [enables 8B LDS pairs for mma frags]
// ---------------------------------------------------------------------------
__device__ float gAhi[(size_t)N_FEAT * K_DIM];
__device__ float gAlo[(size_t)N_FEAT * K_DIM];
__device__ float gBhi[(size_t)M_PROTO * K_DIM];
__device__ float gBlo[(size_t)M_PROTO * K_DIM];
__device__ float g_psq10[M_PROTO];      // 10 * ||p_m||^2

// ---------------------------------------------------------------------------
__device__ __forceinline__ uint32_t smem_u32(const void* p) {
    uint32_t a;
    asm("{ .reg .u64 t; cvta.to.shared.u64 t, %1; cvt.u32.u64 %0, t; }" : "=r"(a) : "l"(p));
    return a;
}
#define CP_ASYNC16(dst, src) \
    asm volatile("cp.async.cg.shared.global [%0], [%1], 16;" :: "r"(dst), "l"(src) : "memory")
#define CP_COMMIT() asm volatile("cp.async.commit_group;" ::: "memory")
#define CP_WAIT(n)  asm volatile("cp.async.wait_group %0;" :: "n"(n) : "memory")

__device__ __forceinline__ uint32_t f2tf32(float x) {
    uint32_t r;
    asm("cvt.rna.tf32.f32 %0, %1;" : "=r"(r) : "f"(x));
    return r;
}

// mma.sync m16n8k8 tf32 (sm_80 baseline feature -> legal on plain sm_100)
__device__ __forceinline__ void mma_tf32(float* d,
                                         uint32_t a0, uint32_t a1, uint32_t a2, uint32_t a3,
                                         uint32_t b0, uint32_t b1) {
    asm volatile(
        "mma.sync.aligned.m16n8k8.row.col.f32.tf32.tf32.f32 "
        "{%0,%1,%2,%3}, {%4,%5,%6,%7}, {%8,%9}, {%0,%1,%2,%3};"
        : "+f"(d[0]), "+f"(d[1]), "+f"(d[2]), "+f"(d[3])
        : "r"(a0), "r"(a1), "r"(a2), "r"(a3), "r"(b0), "r"(b1));
}

// ---------------------------------------------------------------------------
// Split fp32 -> (hi, lo) tf32 with in-group-of-8 k permutation.
// Each thread handles 8 consecutive k (one perm group): fully coalesced.
// physical j holds logical {0,4,1,5,2,6,3,7}[j].
// which == 0 -> write gAhi/gAlo, which == 1 -> write gBhi/gBlo
// ---------------------------------------------------------------------------
__global__ void split_kernel(const float* __restrict__ src, int ngroups, int which) {
    float* hi = which ? gBhi : gAhi;
    float* lo = which ? gBlo : gAlo;
    int g = blockIdx.x * blockDim.x + threadIdx.x;
    if (g >= ngroups) return;
    const float4* s4 = (const float4*)(src + (size_t)g * 8);
    float4 x0 = s4[0], x1 = s4[1];
    float in[8] = {x0.x, x0.y, x0.z, x0.w, x1.x, x1.y, x1.z, x1.w};
    float h[8], l[8];
#pragma unroll
    for (int i = 0; i < 8; i++) {
        uint32_t hb = f2tf32(in[i]);
        h[i] = __uint_as_float(hb);
        l[i] = __uint_as_float(f2tf32(in[i] - h[i]));
    }
    float4 ha  = {h[0], h[4], h[1], h[5]};
    float4 hb4 = {h[2], h[6], h[3], h[7]};
    float4 la  = {l[0], l[4], l[1], l[5]};
    float4 lb  = {l[2], l[6], l[3], l[7]};
    ((float4*)(hi + (size_t)g * 8))[0] = ha;
    ((float4*)(hi + (size_t)g * 8))[1] = hb4;
    ((float4*)(lo + (size_t)g * 8))[0] = la;
    ((float4*)(lo + (size_t)g * 8))[1] = lb;
}

// ---------------------------------------------------------------------------
// 10*||p_m||^2, one warp per row (coalesced float4 + shfl reduce)
// ---------------------------------------------------------------------------
__global__ void psq_kernel(const float* __restrict__ B) {
    int w = (blockIdx.x * blockDim.x + threadIdx.x) >> 5;
    int lane = threadIdx.x & 31;
    if (w >= M_PROTO) return;
    const float4* row = (const float4*)(B + (size_t)w * K_DIM);
    float s = 0.f;
#pragma unroll
    for (int i = 0; i < 4; i++) {
        float4 v = row[lane + i * 32];
        s += v.x * v.x + v.y * v.y + v.z * v.z + v.w * v.w;
    }
#pragma unroll
    for (int o = 16; o > 0; o >>= 1) s += __shfl_xor_sync(0xFFFFFFFFu, s, o);
    if (lane == 0) g_psq10[w] = 10.f * s;
}

// ---------------------------------------------------------------------------
// GEMM: S[n,m] = 20 * dot(feat_n, proto_m) - 10*||p_m||^2
// 3xTF32 emulation: hi*hi + hi*lo + lo*hi, fp32 accumulate on tensor cores.
// CTA 128x128, BK=32 (tf32), 2-stage cp.async pipeline.
// Smem row stride 40 words -> conflict-free 8B fragment loads.
// ---------------------------------------------------------------------------
#define BK        32
#define STRIDE    40
#define ARR_W     (128 * STRIDE)          // words per operand array (5120)
#define STAGE_W   (4 * ARR_W)             // words per stage (20480)
#define SMEM_TOT  (2 * STAGE_W * 4)       // bytes (163840)
#define KT_STEPS  (K_DIM / BK)            // 16

__global__ __launch_bounds__(256, 1)
void gemm_tc_kernel(float* __restrict__ S) {
    extern __shared__ float smem[];
    const uint32_t smem_base = smem_u32(smem);
    const int tid  = threadIdx.x;
    const int wid  = tid >> 5;
    const int lane = tid & 31;
    const int warpM = wid & 1;            // 2 warps in M
    const int warpN = wid >> 1;           // 4 warps in N
    const int m0 = blockIdx.x * 128;      // proto tile
    const int n0 = blockIdx.y * 128;      // feat tile

    const float* gsrc[4] = {
        gAhi + (size_t)n0 * K_DIM,
        gAlo + (size_t)n0 * K_DIM,
        gBhi + (size_t)m0 * K_DIM,
        gBlo + (size_t)m0 * K_DIM
    };

    float acc[4][4][4];
#pragma unroll
    for (int i = 0; i < 4; i++)
#pragma unroll
        for (int j = 0; j < 4; j++)
#pragma unroll
            for (int q = 0; q < 4; q++) acc[i][j][q] = 0.f;

    // ---- stage loader: 16 cp.async per thread ----
    auto load_stage = [&](int buf, int kt) {
#pragma unroll
        for (int arr = 0; arr < 4; arr++) {
#pragma unroll
            for (int it = 0; it < 4; it++) {
                int chunk = tid + it * 256;          // 0..1023
                int row = chunk >> 3;
                int j   = chunk & 7;
                uint32_t dst = smem_base +
                    (uint32_t)(buf * STAGE_W + arr * ARR_W + row * STRIDE + j * 4) * 4u;
                const float* src = gsrc[arr] + (size_t)row * K_DIM + kt * BK + j * 4;
                CP_ASYNC16(dst, src);
            }
        }
        CP_COMMIT();
    };

    load_stage(0, 0);
    load_stage(1, 1);

    const int r  = lane >> 2;
    const int c2 = (lane & 3) * 2;

    for (int kt = 0; kt < KT_STEPS; kt++) {
        const int b = kt & 1;
        CP_WAIT(1);
        __syncthreads();

        const float* sAhi = smem + b * STAGE_W;
        const float* sAlo = sAhi + ARR_W;
        const float* sBhi = sAlo + ARR_W;
        const float* sBlo = sBhi + ARR_W;

#pragma unroll
        for (int ko = 0; ko < 4; ko++) {
            const int kb = ko * 8 + c2;
            uint2 AH[4][2], AL[4][2], BH[4], BL[4];
#pragma unroll
            for (int mt = 0; mt < 4; mt++) {
                int row = warpM * 64 + mt * 16 + r;
                AH[mt][0] = *(const uint2*)(sAhi + row * STRIDE + kb);
                AH[mt][1] = *(const uint2*)(sAhi + (row + 8) * STRIDE + kb);
                AL[mt][0] = *(const uint2*)(sAlo + row * STRIDE + kb);
                AL[mt][1] = *(const uint2*)(sAlo + (row + 8) * STRIDE + kb);
            }
#pragma unroll
            for (int nt = 0; nt < 4; nt++) {
                int col = warpN * 32 + nt * 8 + r;
                BH[nt] = *(const uint2*)(sBhi + col * STRIDE + kb);
                BL[nt] = *(const uint2*)(sBlo + col * STRIDE + kb);
            }
#pragma unroll
            for (int mt = 0; mt < 4; mt++)
#pragma unroll
                for (int nt = 0; nt < 4; nt++) {
                    // a0=(r,c) a1=(r+8,c) a2=(r,c+4) a3=(r+8,c+4)
                    mma_tf32(acc[mt][nt],
                             AH[mt][0].x, AH[mt][1].x, AH[mt][0].y, AH[mt][1].y,
                             BH[nt].x, BH[nt].y);
                    mma_tf32(acc[mt][nt],
                             AH[mt][0].x, AH[mt][1].x, AH[mt][0].y, AH[mt][1].y,
                             BL[nt].x, BL[nt].y);
                    mma_tf32(acc[mt][nt],
                             AL[mt][0].x, AL[mt][1].x, AL[mt][0].y, AL[mt][1].y,
                             BH[nt].x, BH[nt].y);
                }
        }
        __syncthreads();
        if (kt + 2 < KT_STEPS) load_stage(b, kt + 2);
    }

    // ---- epilogue: stage 10*psq for this m-tile, then scaled stores ----
    float* sp = smem;                      // mainloop done; reuse
    __syncthreads();
    if (tid < 128) sp[tid] = g_psq10[m0 + tid];
    __syncthreads();

#pragma unroll
    for (int mt = 0; mt < 4; mt++) {
        int gr = n0 + warpM * 64 + mt * 16 + r;
#pragma unroll
        for (int nt = 0; nt < 4; nt++) {
            int lc = warpN * 32 + nt * 8 + c2;
            float p0 = sp[lc], p1 = sp[lc + 1];
            float2 o0, o1;
            o0.x = 20.f * acc[mt][nt][0] - p0;
            o0.y = 20.f * acc[mt][nt][1] - p1;
            o1.x = 20.f * acc[mt][nt][2] - p0;
            o1.y = 20.f * acc[mt][nt][3] - p1;
            *(float2*)(S + (size_t)gr * M_PROTO + m0 + lc) = o0;
            *(float2*)(S + (size_t)(gr + 8) * M_PROTO + m0 + lc) = o1;
        }
    }
}

// ---------------------------------------------------------------------------
// Row softmax (in place), quality = 1/sum(exp), max_id = first argmax
// ---------------------------------------------------------------------------
__global__ void softmax_kernel(float* __restrict__ S,
                               float* __restrict__ quality,
                               float* __restrict__ maxid) {
    const int row = blockIdx.x;
    float* srow = S + (size_t)row * M_PROTO;
    const int t = threadIdx.x;

    float v[8];
    float4 v0 = *(const float4*)(srow + t * 8 + 0);
    float4 v1 = *(const float4*)(srow + t * 8 + 4);
    v[0] = v0.x; v[1] = v0.y; v[2] = v0.z; v[3] = v0.w;
    v[4] = v1.x; v[5] = v1.y; v[6] = v1.z; v[7] = v1.w;

    float lmax = v[0];
    int   limx = t * 8;
#pragma unroll
    for (int j = 1; j < 8; j++)
        if (v[j] > lmax) { lmax = v[j]; limx = t * 8 + j; }

    __shared__ float smax[256];
    __shared__ int   sidx[256];
    smax[t] = lmax;
    sidx[t] = limx;
    __syncthreads();
#pragma unroll
    for (int s = 128; s > 0; s >>= 1) {
        if (t < s) {
            float v2 = smax[t + s];
            int   i2 = sidx[t + s];
            if (v2 > smax[t] || (v2 == smax[t] && i2 < sidx[t])) {
                smax[t] = v2; sidx[t] = i2;
            }
        }
        __syncthreads();
    }
    const float rowmax = smax[0];
    const int   rowarg = sidx[0];
    __syncthreads();

    float e[8];
    float lsum = 0.f;
#pragma unroll
    for (int j = 0; j < 8; j++) { e[j] = expf(v[j] - rowmax); lsum += e[j]; }
    smax[t] = lsum;
    __syncthreads();
#pragma unroll
    for (int s = 128; s > 0; s >>= 1) {
        if (t < s) smax[t] += smax[t + s];
        __syncthreads();
    }
    const float inv = 1.0f / smax[0];

    float4 o0, o1;
    o0.x = e[0] * inv; o0.y = e[1] * inv; o0.z = e[2] * inv; o0.w = e[3] * inv;
    o1.x = e[4] * inv; o1.y = e[5] * inv; o1.z = e[6] * inv; o1.w = e[7] * inv;
    *(float4*)(srow + t * 8 + 0) = o0;
    *(float4*)(srow + t * 8 + 4) = o1;

    if (t == 0) {
        quality[row] = inv;
        maxid[row]   = (float)rowarg;
    }
}

// ---------------------------------------------------------------------------
extern "C" void kernel_launch(void* const* d_in, const int* in_sizes, int n_in,
                              void* d_out, int out_size) {
    const float* feat  = (const float*)d_in[0];   // [32768, 512]
    const float* proto = (const float*)d_in[1];   // [2048, 512]
    float* out = (float*)d_out;

    float* quality = out;
    float* maxid   = out + N_FEAT;
    float* pred    = out + 2 * N_FEAT;

    // unconditional, idempotent, host-side (no static guards -- harness rule)
    cudaFuncSetAttribute(gemm_tc_kernel,
                         cudaFuncAttributeMaxDynamicSharedMemorySize, SMEM_TOT);

    int gA = N_FEAT * K_DIM / 8;    // perm groups
    int gB = M_PROTO * K_DIM / 8;
    split_kernel<<<(gA + 255) / 256, 256>>>(feat, gA, 0);
    split_kernel<<<(gB + 255) / 256, 256>>>(proto, gB, 1);
    psq_kernel<<<M_PROTO / 8, 256>>>(proto);

    dim3 grid(M_PROTO / 128, N_FEAT / 128);
    gemm_tc_kernel<<<grid, 256, SMEM_TOT>>>(pred);

    softmax_kernel<<<N_FEAT, 256>>>(pred, quality, maxid);
}

// round 5
// speedup vs baseline: 1.6119x; 1.1960x over previous
#include <cuda_runtime.h>
#include <cuda_bf16.h>
#include <math.h>
#include <stdint.h>

// Problem shape (fixed by setup_inputs)
#define N_FEAT  32768
#define M_PROTO 2048
#define K_DIM   512

// ---------------------------------------------------------------------------
// Static device scratch (no cudaMalloc allowed)
// gXhi32: tf32-valued fp32, k-permuted per 8 (phys j = logical {0,4,1,5,2,6,3,7})
// gXhibf/gXlobf: bf16 hi/lo, pair-permuted per 8 pairs (same perm on pair idx)
// ---------------------------------------------------------------------------
__device__ float         gAhi32[(size_t)N_FEAT * K_DIM];
__device__ float         gBhi32[(size_t)M_PROTO * K_DIM];
__device__ __nv_bfloat16 gAhibf[(size_t)N_FEAT * K_DIM];
__device__ __nv_bfloat16 gAlobf[(size_t)N_FEAT * K_DIM];
__device__ __nv_bfloat16 gBhibf[(size_t)M_PROTO * K_DIM];
__device__ __nv_bfloat16 gBlobf[(size_t)M_PROTO * K_DIM];
__device__ float g_psq10[M_PROTO];      // 10 * ||p_m||^2

// ---------------------------------------------------------------------------
__device__ __forceinline__ uint32_t smem_u32(const void* p) {
    uint32_t a;
    asm("{ .reg .u64 t; cvta.to.shared.u64 t, %1; cvt.u32.u64 %0, t; }" : "=r"(a) : "l"(p));
    return a;
}
#define CP_ASYNC16(dst, src) \
    asm volatile("cp.async.cg.shared.global [%0], [%1], 16;" :: "r"(dst), "l"(src) : "memory")
#define CP_COMMIT() asm volatile("cp.async.commit_group;" ::: "memory")
#define CP_WAIT(n)  asm volatile("cp.async.wait_group %0;" :: "n"(n) : "memory")

__device__ __forceinline__ uint32_t f2tf32(float x) {
    uint32_t r;
    asm("cvt.rna.tf32.f32 %0, %1;" : "=r"(r) : "f"(x));
    return r;
}

// mma.sync m16n8k8 tf32 (sm_80 baseline -> legal on plain sm_100)
__device__ __forceinline__ void mma_tf32(float* d,
                                         uint32_t a0, uint32_t a1, uint32_t a2, uint32_t a3,
                                         uint32_t b0, uint32_t b1) {
    asm volatile(
        "mma.sync.aligned.m16n8k8.row.col.f32.tf32.tf32.f32 "
        "{%0,%1,%2,%3}, {%4,%5,%6,%7}, {%8,%9}, {%0,%1,%2,%3};"
        : "+f"(d[0]), "+f"(d[1]), "+f"(d[2]), "+f"(d[3])
        : "r"(a0), "r"(a1), "r"(a2), "r"(a3), "r"(b0), "r"(b1));
}

// mma.sync m16n8k16 bf16 (sm_80 baseline)
__device__ __forceinline__ void mma_bf16(float* d,
                                         uint32_t a0, uint32_t a1, uint32_t a2, uint32_t a3,
                                         uint32_t b0, uint32_t b1) {
    asm volatile(
        "mma.sync.aligned.m16n8k16.row.col.f32.bf16.bf16.f32 "
        "{%0,%1,%2,%3}, {%4,%5,%6,%7}, {%8,%9}, {%0,%1,%2,%3};"
        : "+f"(d[0]), "+f"(d[1]), "+f"(d[2]), "+f"(d[3])
        : "r"(a0), "r"(a1), "r"(a2), "r"(a3), "r"(b0), "r"(b1));
}

// ---------------------------------------------------------------------------
// Split fp32 -> tf32 hi (fp32, permuted per 8) + bf16(hi), bf16(lo)
// (pair-permuted per 8 pairs). One thread = 16 consecutive k of one row.
// ---------------------------------------------------------------------------
__global__ void split_kernel(const float* __restrict__ src, int ngroups, int which) {
    float*         hi32 = which ? gBhi32 : gAhi32;
    __nv_bfloat16* hibf = which ? gBhibf : gAhibf;
    __nv_bfloat16* lobf = which ? gBlobf : gAlobf;
    int g = blockIdx.x * blockDim.x + threadIdx.x;
    if (g >= ngroups) return;

    const float4* s4 = (const float4*)(src + (size_t)g * 16);
    float in[16];
    float4 x0 = s4[0], x1 = s4[1], x2 = s4[2], x3 = s4[3];
    in[0]=x0.x; in[1]=x0.y; in[2]=x0.z; in[3]=x0.w;
    in[4]=x1.x; in[5]=x1.y; in[6]=x1.z; in[7]=x1.w;
    in[8]=x2.x; in[9]=x2.y; in[10]=x2.z; in[11]=x2.w;
    in[12]=x3.x; in[13]=x3.y; in[14]=x3.z; in[15]=x3.w;

    float h[16], l[16];
#pragma unroll
    for (int i = 0; i < 16; i++) {
        h[i] = __uint_as_float(f2tf32(in[i]));
        l[i] = in[i] - h[i];
    }

    // fp32 hi, permuted per 8: phys j holds logical {0,4,1,5,2,6,3,7}[j]
    float4 o0 = {h[0], h[4], h[1], h[5]};
    float4 o1 = {h[2], h[6], h[3], h[7]};
    float4 o2 = {h[8], h[12], h[9], h[13]};
    float4 o3 = {h[10], h[14], h[11], h[15]};
    float4* d4 = (float4*)(hi32 + (size_t)g * 16);
    d4[0] = o0; d4[1] = o1; d4[2] = o2; d4[3] = o3;

    // bf16 pairs (P_j = k{2j,2j+1}), phys pair order {0,4,1,5,2,6,3,7}
    const int pp[8] = {0, 4, 1, 5, 2, 6, 3, 7};
    __nv_bfloat162 wh[8], wl[8];
#pragma unroll
    for (int j = 0; j < 8; j++) {
        int p = pp[j];
        wh[j] = __floats2bfloat162_rn(h[2 * p], h[2 * p + 1]);
        wl[j] = __floats2bfloat162_rn(l[2 * p], l[2 * p + 1]);
    }
    uint4* dh = (uint4*)(hibf + (size_t)g * 16);
    uint4* dl = (uint4*)(lobf + (size_t)g * 16);
    dh[0] = *(uint4*)&wh[0]; dh[1] = *(uint4*)&wh[4];
    dl[0] = *(uint4*)&wl[0]; dl[1] = *(uint4*)&wl[4];
}

// ---------------------------------------------------------------------------
// 10*||p_m||^2, one warp per row
// ---------------------------------------------------------------------------
__global__ void psq_kernel(const float* __restrict__ B) {
    int w = (blockIdx.x * blockDim.x + threadIdx.x) >> 5;
    int lane = threadIdx.x & 31;
    if (w >= M_PROTO) return;
    const float4* row = (const float4*)(B + (size_t)w * K_DIM);
    float s = 0.f;
#pragma unroll
    for (int i = 0; i < 4; i++) {
        float4 v = row[lane + i * 32];
        s += v.x * v.x + v.y * v.y + v.z * v.z + v.w * v.w;
    }
#pragma unroll
    for (int o = 16; o > 0; o >>= 1) s += __shfl_xor_sync(0xFFFFFFFFu, s, o);
    if (lane == 0) g_psq10[w] = 10.f * s;
}

// ---------------------------------------------------------------------------
// GEMM: S[n,m] = 20 * dot(feat_n, proto_m) - 10*||p_m||^2
// Hybrid emulation: hi*hi in tf32 (exact), cross terms hi*lo + lo*hi in bf16.
// CTA 128x128, BK=16, 2-stage cp.async pipeline, 2 CTAs/SM.
// Per-stage smem (words): Ahi32 128x24=3072 | Bhi32 3072 |
//                         Ahibf 1024 | Alobf 1024 | Bhibf 1024 | Blobf 1024
// ---------------------------------------------------------------------------
#define STAGE_W   10240
#define SMEM_TOT  (2 * STAGE_W * 4)       // 81920 bytes
#define KT_STEPS  (K_DIM / 16)            // 32

__global__ __launch_bounds__(256, 2)
void gemm_tc_kernel(float* __restrict__ S) {
    extern __shared__ float smem[];
    const uint32_t smem_base = smem_u32(smem);
    const int tid  = threadIdx.x;
    const int wid  = tid >> 5;
    const int lane = tid & 31;
    const int warpM = wid & 1;            // 2 warps in M (feat)
    const int warpN = wid >> 1;           // 4 warps in N (proto)
    const int m0 = blockIdx.x * 128;
    const int n0 = blockIdx.y * 128;

    float acc[4][4][4];
#pragma unroll
    for (int i = 0; i < 4; i++)
#pragma unroll
        for (int j = 0; j < 4; j++)
#pragma unroll
            for (int q = 0; q < 4; q++) acc[i][j][q] = 0.f;

    // ---- stage loader: 8 cp.async(16B) per thread ----
    auto load_stage = [&](int buf, int kt) {
        uint32_t sb = smem_base + (uint32_t)buf * (STAGE_W * 4);
#pragma unroll
        for (int it = 0; it < 8; it++) {
            int chunk = tid + it * 256;
            if (it < 2) {
                int c = chunk;                       // A hi32: 512 chunks
                int row = c >> 2, j = c & 3;
                uint32_t dst = sb + (uint32_t)(row * 24 + j * 4) * 4u;
                const float* src = gAhi32 + (size_t)(n0 + row) * K_DIM + kt * 16 + j * 4;
                CP_ASYNC16(dst, src);
            } else if (it < 4) {
                int c = chunk - 512;                 // B hi32: 512 chunks
                int row = c >> 2, j = c & 3;
                uint32_t dst = sb + (uint32_t)(3072 + row * 24 + j * 4) * 4u;
                const float* src = gBhi32 + (size_t)(m0 + row) * K_DIM + kt * 16 + j * 4;
                CP_ASYNC16(dst, src);
            } else {
                int arr = it - 4;                    // 0:Ahibf 1:Alobf 2:Bhibf 3:Blobf
                int cc = chunk - 1024 - arr * 256;   // 0..255
                int row = cc >> 1, j = cc & 1;
                uint32_t dst = sb + (uint32_t)(6144 + arr * 1024 + row * 8 + j * 4) * 4u;
                const char* srcb;
                if (arr == 0)
                    srcb = (const char*)gAhibf + ((size_t)(n0 + row) * K_DIM + kt * 16) * 2 + j * 16;
                else if (arr == 1)
                    srcb = (const char*)gAlobf + ((size_t)(n0 + row) * K_DIM + kt * 16) * 2 + j * 16;
                else if (arr == 2)
                    srcb = (const char*)gBhibf + ((size_t)(m0 + row) * K_DIM + kt * 16) * 2 + j * 16;
                else
                    srcb = (const char*)gBlobf + ((size_t)(m0 + row) * K_DIM + kt * 16) * 2 + j * 16;
                CP_ASYNC16(dst, srcb);
            }
        }
        CP_COMMIT();
    };

    load_stage(0, 0);
    load_stage(1, 1);

    const int r  = lane >> 2;
    const int c2 = (lane & 3) * 2;

    for (int kt = 0; kt < KT_STEPS; kt++) {
        const int b = kt & 1;
        CP_WAIT(1);
        __syncthreads();

        const float* st   = smem + b * STAGE_W;
        const float* sA32 = st;
        const float* sB32 = st + 3072;
        const float* sAh  = st + 6144;
        const float* sAl  = st + 7168;
        const float* sBh  = st + 8192;
        const float* sBl  = st + 9216;

        // ---- bf16 cross terms (full k16 in one mma each) ----
        uint2 BHb[4], BLb[4];
#pragma unroll
        for (int nt = 0; nt < 4; nt++) {
            int col = warpN * 32 + nt * 8 + r;
            BHb[nt] = *(const uint2*)(sBh + col * 8 + c2);
            BLb[nt] = *(const uint2*)(sBl + col * 8 + c2);
        }
#pragma unroll
        for (int mt = 0; mt < 4; mt++) {
            int row = warpM * 64 + mt * 16 + r;
            uint2 ah0 = *(const uint2*)(sAh + row * 8 + c2);
            uint2 ah1 = *(const uint2*)(sAh + (row + 8) * 8 + c2);
            uint2 al0 = *(const uint2*)(sAl + row * 8 + c2);
            uint2 al1 = *(const uint2*)(sAl + (row + 8) * 8 + c2);
#pragma unroll
            for (int nt = 0; nt < 4; nt++) {
                mma_bf16(acc[mt][nt], ah0.x, ah1.x, ah0.y, ah1.y, BLb[nt].x, BLb[nt].y);
                mma_bf16(acc[mt][nt], al0.x, al1.x, al0.y, al1.y, BHb[nt].x, BHb[nt].y);
            }
        }

        // ---- tf32 hi*hi (two k8 steps) ----
#pragma unroll
        for (int ko = 0; ko < 2; ko++) {
            const int kb = ko * 8 + c2;
            uint2 BH[4];
#pragma unroll
            for (int nt = 0; nt < 4; nt++) {
                int col = warpN * 32 + nt * 8 + r;
                BH[nt] = *(const uint2*)(sB32 + col * 24 + kb);
            }
#pragma unroll
            for (int mt = 0; mt < 4; mt++) {
                int row = warpM * 64 + mt * 16 + r;
                uint2 a0 = *(const uint2*)(sA32 + row * 24 + kb);
                uint2 a1 = *(const uint2*)(sA32 + (row + 8) * 24 + kb);
#pragma unroll
                for (int nt = 0; nt < 4; nt++)
                    mma_tf32(acc[mt][nt], a0.x, a1.x, a0.y, a1.y, BH[nt].x, BH[nt].y);
            }
        }

        __syncthreads();
        if (kt + 2 < KT_STEPS) load_stage(b, kt + 2);
    }

    // ---- epilogue ----
    float* sp = smem;
    __syncthreads();
    if (tid < 128) sp[tid] = g_psq10[m0 + tid];
    __syncthreads();

#pragma unroll
    for (int mt = 0; mt < 4; mt++) {
        int gr = n0 + warpM * 64 + mt * 16 + r;
#pragma unroll
        for (int nt = 0; nt < 4; nt++) {
            int lc = warpN * 32 + nt * 8 + c2;
            float p0 = sp[lc], p1 = sp[lc + 1];
            float2 o0, o1;
            o0.x = 20.f * acc[mt][nt][0] - p0;
            o0.y = 20.f * acc[mt][nt][1] - p1;
            o1.x = 20.f * acc[mt][nt][2] - p0;
            o1.y = 20.f * acc[mt][nt][3] - p1;
            *(float2*)(S + (size_t)gr * M_PROTO + m0 + lc) = o0;
            *(float2*)(S + (size_t)(gr + 8) * M_PROTO + m0 + lc) = o1;
        }
    }
}

// ---------------------------------------------------------------------------
// Row softmax (in place), quality = 1/sum(exp), max_id = first argmax
// ---------------------------------------------------------------------------
__global__ void softmax_kernel(float* __restrict__ S,
                               float* __restrict__ quality,
                               float* __restrict__ maxid) {
    const int row = blockIdx.x;
    float* srow = S + (size_t)row * M_PROTO;
    const int t = threadIdx.x;

    float v[8];
    float4 v0 = *(const float4*)(srow + t * 8 + 0);
    float4 v1 = *(const float4*)(srow + t * 8 + 4);
    v[0] = v0.x; v[1] = v0.y; v[2] = v0.z; v[3] = v0.w;
    v[4] = v1.x; v[5] = v1.y; v[6] = v1.z; v[7] = v1.w;

    float lmax = v[0];
    int   limx = t * 8;
#pragma unroll
    for (int j = 1; j < 8; j++)
        if (v[j] > lmax) { lmax = v[j]; limx = t * 8 + j; }

    __shared__ float smax[256];
    __shared__ int   sidx[256];
    smax[t] = lmax;
    sidx[t] = limx;
    __syncthreads();
#pragma unroll
    for (int s = 128; s > 0; s >>= 1) {
        if (t < s) {
            float v2 = smax[t + s];
            int   i2 = sidx[t + s];
            if (v2 > smax[t] || (v2 == smax[t] && i2 < sidx[t])) {
                smax[t] = v2; sidx[t] = i2;
            }
        }
        __syncthreads();
    }
    const float rowmax = smax[0];
    const int   rowarg = sidx[0];
    __syncthreads();

    float e[8];
    float lsum = 0.f;
#pragma unroll
    for (int j = 0; j < 8; j++) { e[j] = expf(v[j] - rowmax); lsum += e[j]; }
    smax[t] = lsum;
    __syncthreads();
#pragma unroll
    for (int s = 128; s > 0; s >>= 1) {
        if (t < s) smax[t] += smax[t + s];
        __syncthreads();
    }
    const float inv = 1.0f / smax[0];

    float4 o0, o1;
    o0.x = e[0] * inv; o0.y = e[1] * inv; o0.z = e[2] * inv; o0.w = e[3] * inv;
    o1.x = e[4] * inv; o1.y = e[5] * inv; o1.z = e[6] * inv; o1.w = e[7] * inv;
    *(float4*)(srow + t * 8 + 0) = o0;
    *(float4*)(srow + t * 8 + 4) = o1;

    if (t == 0) {
        quality[row] = inv;
        maxid[row]   = (float)rowarg;
    }
}

// ---------------------------------------------------------------------------
extern "C" void kernel_launch(void* const* d_in, const int* in_sizes, int n_in,
                              void* d_out, int out_size) {
    const float* feat  = (const float*)d_in[0];   // [32768, 512]
    const float* proto = (const float*)d_in[1];   // [2048, 512]
    float* out = (float*)d_out;

    float* quality = out;
    float* maxid   = out + N_FEAT;
    float* pred    = out + 2 * N_FEAT;

    cudaFuncSetAttribute(gemm_tc_kernel,
                         cudaFuncAttributeMaxDynamicSharedMemorySize, SMEM_TOT);

    int gA = N_FEAT * K_DIM / 16;
    int gB = M_PROTO * K_DIM / 16;
    split_kernel<<<(gA + 255) / 256, 256>>>(feat, gA, 0);
    split_kernel<<<(gB + 255) / 256, 256>>>(proto, gB, 1);
    psq_kernel<<<M_PROTO / 8, 256>>>(proto);

    dim3 grid(M_PROTO / 128, N_FEAT / 128);
    gemm_tc_kernel<<<grid, 256, SMEM_TOT>>>(pred);

    softmax_kernel<<<N_FEAT, 256>>>(pred, quality, maxid);
}